// round 4
// baseline (speedup 1.0000x reference)
#include <cuda_runtime.h>
#include <math.h>

#define B 4
#define C 192
#define HEADS 4
#define DH 32
#define HID 128
#define NMEM 4
#define QT 16
#define SQRTC 13.856406460551018f
#define SCALE 0.17677669529663687f

// ---------------- scratch ----------------------------------------------------
__device__ float g_w[B*160*160];
__device__ float g_rowft[B*C*160];
__device__ float g_colft[B*C*160];
__device__ float g_vbr[B*C*160];
__device__ float g_vbc[B*C*160];
__device__ float g_part[2][6][B*HEADS*160*DH];  // [ksplit][which]
__device__ float g_qkv[6][B*HEADS*160*DH];      // which = ax*3 + {q,k,v}
__device__ float g_hoT[2][B*HID*160];           // [(b*128+hid)*160 + pos]
__device__ float g_E[2][C*HID];
__device__ float g_e[2][C];
__device__ float g_F[2][B][C][160];             // folded outputs incl bias

// ---------------- K0: fold Wr@Wo, Wr@bo --------------------------------------
__global__ void k_fold(const float* __restrict__ Wr, const float* __restrict__ Wo,
                       const float* __restrict__ bo) {
    int ax = blockIdx.x, d0 = blockIdx.y * 8;
    __shared__ float Wrs[8][192];
    int t = threadIdx.x;  // 128
    for (int idx = t; idx < 8*192; idx += 128) {
        int j = idx / 192, c = idx % 192;
        Wrs[j][c] = Wr[(d0 + j)*2*C + ax*C + c];
    }
    __syncthreads();
    float acc[8] = {0,0,0,0,0,0,0,0};
    #pragma unroll 4
    for (int c = 0; c < C; c++) {
        float wo = Wo[c*HID + t];
        #pragma unroll
        for (int j = 0; j < 8; j++) acc[j] += Wrs[j][c] * wo;
    }
    #pragma unroll
    for (int j = 0; j < 8; j++) g_E[ax][(d0 + j)*HID + t] = acc[j];
    if (t < 8) {
        float e = 0.f;
        for (int c = 0; c < C; c++) e += Wrs[t][c] * bo[c];
        g_e[ax][d0 + t] = e;
    }
}

// ---------------- K1: per-pixel channel norms -> w ---------------------------
__global__ void k_norm(const float* __restrict__ x) {
    int b = blockIdx.x / 160, n = blockIdx.x % 160, m = threadIdx.x;
    const float* xp = x + ((size_t)b*C*160 + n)*160 + m;
    float ss = 0.f;
    #pragma unroll 8
    for (int c = 0; c < C; c++) { float v = xp[(size_t)c*25600]; ss += v*v; }
    g_w[(b*160 + n)*160 + m] = SQRTC / fmaxf(sqrtf(ss), 1e-12f);
}

// ---------------- K2: one pass over x -> row_ft, col_ft, vbr, vbc ------------
__global__ void __launch_bounds__(256) k_reduce(const float* __restrict__ x,
                                                const float* __restrict__ gv) {
    int b = blockIdx.x / C, c = blockIdx.x % C;
    int lane = threadIdx.x & 31, warp = threadIdx.x >> 5;   // 8 warps
    const float* xp = x + (size_t)(b*C + c)*25600;
    const float* wp = g_w + b*25600;
    float gvc = gv[c];
    float4 colA = {0,0,0,0}, vrA = {0,0,0,0}, colB = {0,0,0,0}, vrB = {0,0,0,0};
    for (int i = 0; i < 20; i++) {
        int n = warp*20 + i;
        const float4* xp4 = (const float4*)(xp + n*160);
        const float4* wp4 = (const float4*)(wp + n*160);
        float4 xa = xp4[lane], wa = wp4[lane];
        float rs  = xa.x + xa.y + xa.z + xa.w;
        float vcs = xa.x*wa.x + xa.y*wa.y + xa.z*wa.z + xa.w*wa.w;
        colA.x += xa.x; colA.y += xa.y; colA.z += xa.z; colA.w += xa.w;
        vrA.x += xa.x*wa.x; vrA.y += xa.y*wa.y; vrA.z += xa.z*wa.z; vrA.w += xa.w*wa.w;
        if (lane < 8) {
            float4 xb = xp4[32 + lane], wb = wp4[32 + lane];
            rs  += xb.x + xb.y + xb.z + xb.w;
            vcs += xb.x*wb.x + xb.y*wb.y + xb.z*wb.z + xb.w*wb.w;
            colB.x += xb.x; colB.y += xb.y; colB.z += xb.z; colB.w += xb.w;
            vrB.x += xb.x*wb.x; vrB.y += xb.y*wb.y; vrB.z += xb.z*wb.z; vrB.w += xb.w*wb.w;
        }
        #pragma unroll
        for (int o = 16; o; o >>= 1) {
            rs  += __shfl_xor_sync(0xffffffffu, rs,  o);
            vcs += __shfl_xor_sync(0xffffffffu, vcs, o);
        }
        if (!lane) {
            g_rowft[(b*C + c)*160 + n] = rs * (1.0f/160.0f);
            g_vbc  [(b*C + c)*160 + n] = gvc * vcs;
        }
    }
    __shared__ float scol[8][160], svr[8][160];
    *(float4*)&scol[warp][lane*4] = colA;
    *(float4*)&svr [warp][lane*4] = vrA;
    if (lane < 8) {
        *(float4*)&scol[warp][128 + lane*4] = colB;
        *(float4*)&svr [warp][128 + lane*4] = vrB;
    }
    __syncthreads();
    if (threadIdx.x < 160) {
        int m = threadIdx.x;
        float cs = 0.f, vr = 0.f;
        #pragma unroll
        for (int w2 = 0; w2 < 8; w2++) { cs += scol[w2][m]; vr += svr[w2][m]; }
        g_colft[(b*C + c)*160 + m] = cs * (1.0f/160.0f);
        g_vbr  [(b*C + c)*160 + m] = gvc * vr;
    }
}

// ---------------- K3: projections, split-K=2, norms inline -------------------
__global__ void __launch_bounds__(256) k_proj(
        const float* __restrict__ Wq, const float* __restrict__ Wk,
        const float* __restrict__ Wv, const float* __restrict__ gq,
        const float* __restrict__ gk) {
    int which = blockIdx.y, z = blockIdx.z;
    int p0 = blockIdx.x * 32;
    int b = p0 / 160, q0 = p0 % 160;
    const float *src, *W, *gvec = 0;
    float factor = 1.f;
    switch (which) {
        case 0: src=g_rowft; W=Wq; gvec=gq; factor=SCALE*SQRTC; break;
        case 1: src=g_colft; W=Wk; gvec=gk; factor=SQRTC;       break;
        case 2: src=g_vbr;   W=Wv;                               break;
        case 3: src=g_colft; W=Wq; gvec=gq; factor=SCALE*SQRTC; break;
        case 4: src=g_rowft; W=Wk; gvec=gk; factor=SQRTC;       break;
        default:src=g_vbc;   W=Wv;                               break;
    }
    float* out = g_part[z][which];
    __shared__ __align__(16) float Xs[192][36];
    __shared__ __align__(16) float Wsm[32][132];
    __shared__ float red[8][32];
    __shared__ float fs[32];
    int t = threadIdx.x;
    for (int idx = t; idx < 192*32; idx += 256) {
        int c = idx >> 5, pp = idx & 31;
        Xs[c][pp] = src[(b*C + c)*160 + q0 + pp];
    }
    __syncthreads();
    if (gvec) {
        int p = t & 31, cg = t >> 5;
        float ssp = 0.f;
        #pragma unroll 4
        for (int c = cg; c < 192; c += 8) { float v = Xs[c][p]; ssp += v*v; }
        red[cg][p] = ssp;
    }
    __syncthreads();
    if (t < 32) {
        if (gvec) {
            float ss = 0.f;
            #pragma unroll
            for (int j = 0; j < 8; j++) ss += red[j][t];
            fs[t] = factor / fmaxf(sqrtf(ss), 1e-12f);
        } else fs[t] = 1.f;
    }
    int d0 = (t & 31) * 4, pl = (t >> 5) * 4;
    float4 acc0 = {0,0,0,0}, acc1 = {0,0,0,0}, acc2 = {0,0,0,0}, acc3 = {0,0,0,0};
    int cbase = z * 96;
    for (int cc0 = 0; cc0 < 96; cc0 += 32) {
        int c0 = cbase + cc0;
        __syncthreads();
        for (int idx = t; idx < 32*128; idx += 256) {
            int dim = idx >> 5, k = idx & 31;
            float wv = W[dim*C + c0 + k];
            if (gvec) wv *= gvec[c0 + k];
            Wsm[k][dim] = wv;
        }
        __syncthreads();
        #pragma unroll
        for (int k = 0; k < 32; k++) {
            float4 wv = *(const float4*)&Wsm[k][d0];
            float4 xv = *(const float4*)&Xs[c0 + k][pl];
            acc0.x += wv.x*xv.x; acc0.y += wv.y*xv.x; acc0.z += wv.z*xv.x; acc0.w += wv.w*xv.x;
            acc1.x += wv.x*xv.y; acc1.y += wv.y*xv.y; acc1.z += wv.z*xv.y; acc1.w += wv.w*xv.y;
            acc2.x += wv.x*xv.z; acc2.y += wv.y*xv.z; acc2.z += wv.z*xv.z; acc2.w += wv.w*xv.z;
            acc3.x += wv.x*xv.w; acc3.y += wv.y*xv.w; acc3.z += wv.z*xv.w; acc3.w += wv.w*xv.w;
        }
    }
    int h = d0 >> 5, dd = d0 & 31;
    float4 accs[4] = {acc0, acc1, acc2, acc3};
    #pragma unroll
    for (int pg = 0; pg < 4; pg++) {
        float f = fs[pl + pg];
        float4 v = accs[pg];
        v.x *= f; v.y *= f; v.z *= f; v.w *= f;
        *(float4*)&out[((b*HEADS + h)*160 + q0 + pl + pg)*DH + dd] = v;
    }
}

// ---------------- K3b: merge split-K partials ---------------------------------
__global__ void k_merge() {
    int w = blockIdx.y;
    int i = blockIdx.x * 256 + threadIdx.x;   // 20480 float4
    float4 a = ((const float4*)g_part[0][w])[i];
    float4 b = ((const float4*)g_part[1][w])[i];
    float4 r = {a.x + b.x, a.y + b.y, a.z + b.z, a.w + b.w};
    ((float4*)g_qkv[w])[i] = r;
}

// ---------------- K4: attention -----------------------------------------------
__global__ void __launch_bounds__(256) k_attn(const float* __restrict__ memkv) {
    int axial = blockIdx.z, bh = blockIdx.y, qt = blockIdx.x;
    int h = bh & 3, b = bh >> 2;
    const float* Q = g_qkv[3*axial + 0] + (bh*160 + qt*QT)*DH;
    const float* K = g_qkv[3*axial + 1] + bh*160*DH;
    const float* V = g_qkv[3*axial + 2] + bh*160*DH;

    extern __shared__ float dyn[];
    float (*Ks)[36]  = (float(*)[36])(dyn);           // 164x36
    float (*Vs)[36]  = (float(*)[36])(dyn + 5904);    // 164x36
    float (*Qs)[36]  = (float(*)[36])(dyn + 11808);   // 16x36
    float (*S)[168]  = (float(*)[168])(dyn + 12384);  // 16x168
    float* invZ      = dyn + 15072;                   // 16
    float (*Ob)[17]  = (float(*)[17])(dyn + 15088);   // 32x17

    int tid = threadIdx.x, warp = tid >> 5, lane = tid & 31;
    for (int i4 = tid; i4 < 1280; i4 += 256) {
        float4 kv = ((const float4*)K)[i4];
        float4 vv = ((const float4*)V)[i4];
        int r = i4 >> 3, cc = (i4 & 7) * 4;
        *(float4*)&Ks[r][cc] = kv;
        *(float4*)&Vs[r][cc] = vv;
    }
    if (tid < 128) {
        int i4 = tid;
        float4 mk = ((const float4*)(memkv + h*NMEM*DH))[i4 & 31];
        float4 mv = ((const float4*)(memkv + HEADS*NMEM*DH + h*NMEM*DH))[i4 & 31];
        int r = 160 + ((i4 & 31) >> 3), cc = (i4 & 7) * 4;
        if (i4 < 32)       *(float4*)&Ks[r][cc] = mk;
        else if (i4 < 64)  *(float4*)&Vs[r][cc] = mv;
    }
    for (int i4 = tid; i4 < 128; i4 += 256) {
        float4 qv = ((const float4*)Q)[i4];
        int r = i4 >> 3, cc = (i4 & 7) * 4;
        *(float4*)&Qs[r][cc] = qv;
    }
    __syncthreads();

    int qr = warp * 2;
    float s0[6], s1[6];
    #pragma unroll
    for (int j = 0; j < 6; j++) {
        int k = lane + 32*j;
        float a0 = 0.f, a1 = 0.f;
        if (k < 164) {
            #pragma unroll
            for (int d4 = 0; d4 < 8; d4++) {
                float4 kv = *(const float4*)&Ks[k][d4*4];
                float4 qa = *(const float4*)&Qs[qr][d4*4];
                float4 qb = *(const float4*)&Qs[qr+1][d4*4];
                a0 += qa.x*kv.x + qa.y*kv.y + qa.z*kv.z + qa.w*kv.w;
                a1 += qb.x*kv.x + qb.y*kv.y + qb.z*kv.z + qb.w*kv.w;
            }
        }
        s0[j] = a0; s1[j] = a1;
    }
    float mx0 = -1e30f, mx1 = -1e30f;
    #pragma unroll
    for (int j = 0; j < 6; j++)
        if (lane + 32*j < 164) { mx0 = fmaxf(mx0, s0[j]); mx1 = fmaxf(mx1, s1[j]); }
    #pragma unroll
    for (int o = 16; o; o >>= 1) {
        mx0 = fmaxf(mx0, __shfl_xor_sync(0xffffffffu, mx0, o));
        mx1 = fmaxf(mx1, __shfl_xor_sync(0xffffffffu, mx1, o));
    }
    float z0 = 0.f, z1 = 0.f;
    #pragma unroll
    for (int j = 0; j < 6; j++) {
        int k = lane + 32*j;
        if (k < 164) {
            float wgt = (k < 160) ? 160.0f : 1.0f;
            float e0 = __expf(s0[j] - mx0), e1 = __expf(s1[j] - mx1);
            S[qr][k] = e0; S[qr+1][k] = e1;
            z0 += wgt*e0; z1 += wgt*e1;
        }
    }
    #pragma unroll
    for (int o = 16; o; o >>= 1) {
        z0 += __shfl_xor_sync(0xffffffffu, z0, o);
        z1 += __shfl_xor_sync(0xffffffffu, z1, o);
    }
    if (!lane) { invZ[qr] = 1.0f / z0; invZ[qr+1] = 1.0f / z1; }
    __syncwarp();

    float acc0 = 0.f, acc1 = 0.f;
    #pragma unroll 4
    for (int k4 = 0; k4 < 41; k4++) {
        float4 e0 = *(const float4*)&S[qr][k4*4];
        float4 e1 = *(const float4*)&S[qr+1][k4*4];
        float v0 = Vs[k4*4+0][lane], v1 = Vs[k4*4+1][lane];
        float v2 = Vs[k4*4+2][lane], v3 = Vs[k4*4+3][lane];
        acc0 += e0.x*v0 + e0.y*v1 + e0.z*v2 + e0.w*v3;
        acc1 += e1.x*v0 + e1.y*v1 + e1.z*v2 + e1.w*v3;
    }
    Ob[lane][qr]     = acc0 * invZ[qr];
    Ob[lane][qr + 1] = acc1 * invZ[qr + 1];
    __syncthreads();
    float* outp = g_hoT[axial] + (size_t)(b*HID + h*DH)*160 + qt*QT;
    for (int idx = tid; idx < 32*QT; idx += 256) {
        int d = idx >> 4, q = idx & 15;
        outp[d*160 + q] = Ob[d][q];
    }
}

// ---------------- K5: F = E @ hoT  (+bias) -------------------------------------
__global__ void __launch_bounds__(256) k_fgemm() {
    int dch = blockIdx.x, b = blockIdx.y, ax = blockIdx.z;
    int d0 = dch * 16;
    __shared__ float Es[16][128];
    __shared__ __align__(16) float Hs[32][164];
    int t = threadIdx.x;
    for (int idx = t; idx < 16*128; idx += 256)
        Es[idx >> 7][idx & 127] = g_E[ax][(d0 + (idx >> 7))*HID + (idx & 127)];
    int dl = t >> 4, pg = t & 15;
    float acc[10];
    #pragma unroll
    for (int i = 0; i < 10; i++) acc[i] = 0.f;
    const float* hoT = g_hoT[ax] + (size_t)b*HID*160;
    for (int h0 = 0; h0 < HID; h0 += 32) {
        __syncthreads();
        for (int i4 = t; i4 < 1280; i4 += 256) {
            int hl = i4 / 40, p4 = i4 % 40;
            *(float4*)&Hs[hl][p4*4] = *(const float4*)&hoT[(h0 + hl)*160 + p4*4];
        }
        __syncthreads();
        #pragma unroll 8
        for (int hl = 0; hl < 32; hl++) {
            float e = Es[dl][h0 + hl];
            #pragma unroll
            for (int i = 0; i < 10; i++) acc[i] += e * Hs[hl][pg + 16*i];
        }
    }
    float bias = g_e[ax][d0 + dl];
    #pragma unroll
    for (int i = 0; i < 10; i++)
        g_F[ax][b][d0 + dl][pg + 16*i] = acc[i] + bias;
}

// ---------------- K6: pure broadcast write -------------------------------------
__global__ void __launch_bounds__(320) k_final(float* __restrict__ out) {
    int d = blockIdx.x, b = blockIdx.y;
    __shared__ __align__(16) float Fr[160], Fc[160];
    int t = threadIdx.x;  // 320
    if (t < 160) Fr[t] = g_F[0][b][d][t];
    else Fc[t - 160] = g_F[1][b][d][t - 160];
    __syncthreads();
    int m4 = t % 40, ng = t / 40;   // ng in [0,8)
    float4 cv = *(const float4*)&Fc[m4*4];
    float* op = out + ((size_t)(b*C + d)*160)*160 + m4*4;
    #pragma unroll 5
    for (int i = 0; i < 20; i++) {
        int n = ng + 8*i;
        float r = Fr[n];
        float4 v = {r + cv.x, r + cv.y, r + cv.z, r + cv.w};
        *(float4*)&op[(size_t)n*160] = v;
    }
}

// ---------------- launch --------------------------------------------------------
extern "C" void kernel_launch(void* const* d_in, const int* in_sizes, int n_in,
                              void* d_out, int out_size) {
    const float* x     = (const float*)d_in[0];
    const float* gq    = (const float*)d_in[1];
    const float* gk    = (const float*)d_in[2];
    const float* gv    = (const float*)d_in[3];
    const float* Wq    = (const float*)d_in[4];
    const float* Wk    = (const float*)d_in[5];
    const float* Wv    = (const float*)d_in[6];
    const float* memkv = (const float*)d_in[7];
    const float* Wo    = (const float*)d_in[8];
    const float* bo    = (const float*)d_in[9];
    const float* Wr    = (const float*)d_in[10];
    float* out = (float*)d_out;

    cudaFuncSetAttribute(k_attn, cudaFuncAttributeMaxDynamicSharedMemorySize, 62528);

    k_fold  <<<dim3(2, 24), 128>>>(Wr, Wo, bo);
    k_norm  <<<B*160, 160>>>(x);
    k_reduce<<<B*C, 256>>>(x, gv);
    k_proj  <<<dim3(20, 6, 2), 256>>>(Wq, Wk, Wv, gq, gk);
    k_merge <<<dim3(80, 6), 256>>>();
    k_attn  <<<dim3(10, 16, 2), 256, 62528>>>(memkv);
    k_fgemm <<<dim3(12, 4, 2), 256>>>();
    k_final <<<dim3(192, 4), 320>>>(out);
}

// round 5
// speedup vs baseline: 1.0542x; 1.0542x over previous
#include <cuda_runtime.h>
#include <math.h>

#define B 4
#define C 192
#define HEADS 4
#define DH 32
#define HID 128
#define NMEM 4
#define QT 16
#define SQRTC 13.856406460551018f
#define SCALE 0.17677669529663687f

// ---------------- scratch ----------------------------------------------------
__device__ float g_w[B*160*160];
__device__ float g_rowft[B*C*160];
__device__ float g_colft[B*C*160];
__device__ float g_vbr[B*C*160];
__device__ float g_vbc[B*C*160];
__device__ float g_qkv[6][B*HEADS*160*DH];   // ax*3 + {q,k,v}
__device__ float g_hoT[2][B*HID*160];        // [(b*128+hid)*160 + pos]
__device__ float g_E[2][C*HID];
__device__ float g_e[2][C];

// ---------------- K1: fused fold (blocks 0..47) + pixel norms (48..687) ------
__global__ void k_pre(const float* __restrict__ x, const float* __restrict__ Wr,
                      const float* __restrict__ Wo, const float* __restrict__ bo) {
    int bi = blockIdx.x;
    int t = threadIdx.x;  // 160
    if (bi < 48) {
        int ax = bi & 1, d0 = (bi >> 1) * 8;
        __shared__ float Wrs[8][192];
        for (int idx = t; idx < 8*192; idx += 160) {
            int j = idx / 192, c = idx % 192;
            Wrs[j][c] = Wr[(d0 + j)*2*C + ax*C + c];
        }
        __syncthreads();
        if (t < 128) {
            float acc[8] = {0,0,0,0,0,0,0,0};
            #pragma unroll 4
            for (int c = 0; c < C; c++) {
                float wo = Wo[c*HID + t];
                #pragma unroll
                for (int j = 0; j < 8; j++) acc[j] += Wrs[j][c] * wo;
            }
            #pragma unroll
            for (int j = 0; j < 8; j++) g_E[ax][(d0 + j)*HID + t] = acc[j];
        }
        if (t < 8) {
            float e = 0.f;
            for (int c = 0; c < C; c++) e += Wrs[t][c] * bo[c];
            g_e[ax][d0 + t] = e;
        }
    } else {
        int pb = bi - 48;
        int b = pb / 160, n = pb % 160, m = t;
        const float* xp = x + ((size_t)b*C*160 + n)*160 + m;
        float ss = 0.f;
        #pragma unroll 8
        for (int c = 0; c < C; c++) { float v = xp[(size_t)c*25600]; ss += v*v; }
        g_w[(b*160 + n)*160 + m] = SQRTC / fmaxf(sqrtf(ss), 1e-12f);
    }
}

// ---------------- K2: one pass over x -> row_ft, col_ft, vbr, vbc ------------
__global__ void __launch_bounds__(256) k_reduce(const float* __restrict__ x,
                                                const float* __restrict__ gv) {
    int b = blockIdx.x / C, c = blockIdx.x % C;
    int lane = threadIdx.x & 31, warp = threadIdx.x >> 5;   // 8 warps
    const float* xp = x + (size_t)(b*C + c)*25600;
    const float* wp = g_w + b*25600;
    float gvc = gv[c];
    float4 colA = {0,0,0,0}, vrA = {0,0,0,0}, colB = {0,0,0,0}, vrB = {0,0,0,0};
    for (int i = 0; i < 20; i++) {
        int n = warp*20 + i;
        const float4* xp4 = (const float4*)(xp + n*160);
        const float4* wp4 = (const float4*)(wp + n*160);
        float4 xa = xp4[lane], wa = wp4[lane];
        float rs  = xa.x + xa.y + xa.z + xa.w;
        float vcs = xa.x*wa.x + xa.y*wa.y + xa.z*wa.z + xa.w*wa.w;
        colA.x += xa.x; colA.y += xa.y; colA.z += xa.z; colA.w += xa.w;
        vrA.x += xa.x*wa.x; vrA.y += xa.y*wa.y; vrA.z += xa.z*wa.z; vrA.w += xa.w*wa.w;
        if (lane < 8) {
            float4 xb = xp4[32 + lane], wb = wp4[32 + lane];
            rs  += xb.x + xb.y + xb.z + xb.w;
            vcs += xb.x*wb.x + xb.y*wb.y + xb.z*wb.z + xb.w*wb.w;
            colB.x += xb.x; colB.y += xb.y; colB.z += xb.z; colB.w += xb.w;
            vrB.x += xb.x*wb.x; vrB.y += xb.y*wb.y; vrB.z += xb.z*wb.z; vrB.w += xb.w*wb.w;
        }
        #pragma unroll
        for (int o = 16; o; o >>= 1) {
            rs  += __shfl_xor_sync(0xffffffffu, rs,  o);
            vcs += __shfl_xor_sync(0xffffffffu, vcs, o);
        }
        if (!lane) {
            g_rowft[(b*C + c)*160 + n] = rs * (1.0f/160.0f);
            g_vbc  [(b*C + c)*160 + n] = gvc * vcs;
        }
    }
    __shared__ float scol[8][160], svr[8][160];
    *(float4*)&scol[warp][lane*4] = colA;
    *(float4*)&svr [warp][lane*4] = vrA;
    if (lane < 8) {
        *(float4*)&scol[warp][128 + lane*4] = colB;
        *(float4*)&svr [warp][128 + lane*4] = vrB;
    }
    __syncthreads();
    if (threadIdx.x < 160) {
        int m = threadIdx.x;
        float cs = 0.f, vr = 0.f;
        #pragma unroll
        for (int w2 = 0; w2 < 8; w2++) { cs += scol[w2][m]; vr += svr[w2][m]; }
        g_colft[(b*C + c)*160 + m] = cs * (1.0f/160.0f);
        g_vbr  [(b*C + c)*160 + m] = gvc * vr;
    }
}

// ---------------- K3: projections, 8-pos tiles, no split-K -------------------
__global__ void __launch_bounds__(256) k_proj(
        const float* __restrict__ Wq, const float* __restrict__ Wk,
        const float* __restrict__ Wv, const float* __restrict__ gq,
        const float* __restrict__ gk) {
    int which = blockIdx.y;
    int p0 = blockIdx.x * 8;     // 80 tiles
    int b = p0 / 160, q0 = p0 % 160;
    const float *src, *W, *gvec = 0;
    float factor = 1.f;
    switch (which) {
        case 0: src=g_rowft; W=Wq; gvec=gq; factor=SCALE*SQRTC; break;
        case 1: src=g_colft; W=Wk; gvec=gk; factor=SQRTC;       break;
        case 2: src=g_vbr;   W=Wv;                               break;
        case 3: src=g_colft; W=Wq; gvec=gq; factor=SCALE*SQRTC; break;
        case 4: src=g_rowft; W=Wk; gvec=gk; factor=SQRTC;       break;
        default:src=g_vbc;   W=Wv;                               break;
    }
    float* out = g_qkv[which];
    __shared__ float Xs[192][9];
    __shared__ __align__(16) float Wsm[32][132];
    __shared__ float red[32][8];
    __shared__ float fs[8];
    int t = threadIdx.x;
    for (int idx = t; idx < 192*8; idx += 256) {
        int c = idx >> 3, p = idx & 7;
        Xs[c][p] = src[(b*C + c)*160 + q0 + p];
    }
    __syncthreads();
    if (gvec) {
        int p = t & 7, cg = t >> 3;   // 32 groups of 6 channels
        float ssp = 0.f;
        #pragma unroll
        for (int c = cg; c < 192; c += 32) { float v = Xs[c][p]; ssp += v*v; }
        red[cg][p] = ssp;
    }
    __syncthreads();
    if (t < 8) {
        if (gvec) {
            float ss = 0.f;
            #pragma unroll
            for (int j = 0; j < 32; j++) ss += red[j][t];
            fs[t] = factor / fmaxf(sqrtf(ss), 1e-12f);
        } else fs[t] = 1.f;
    }
    int d0 = (t & 31) * 4, pl = t >> 5;
    float4 acc = {0,0,0,0};
    for (int c0 = 0; c0 < 192; c0 += 32) {
        __syncthreads();
        for (int idx = t; idx < 32*128; idx += 256) {
            int dim = idx >> 5, k = idx & 31;
            float wv = W[dim*C + c0 + k];
            if (gvec) wv *= gvec[c0 + k];
            Wsm[k][dim] = wv;
        }
        __syncthreads();
        #pragma unroll
        for (int k = 0; k < 32; k++) {
            float4 wv = *(const float4*)&Wsm[k][d0];
            float xv = Xs[c0 + k][pl];
            acc.x += wv.x*xv; acc.y += wv.y*xv; acc.z += wv.z*xv; acc.w += wv.w*xv;
        }
    }
    __syncthreads();
    int h = d0 >> 5, dd = d0 & 31;
    float f = fs[pl];
    acc.x *= f; acc.y *= f; acc.z *= f; acc.w *= f;
    *(float4*)&out[((b*HEADS + h)*160 + q0 + pl)*DH + dd] = acc;
}

// ---------------- K4: attention -----------------------------------------------
__global__ void __launch_bounds__(256) k_attn(const float* __restrict__ memkv) {
    int axial = blockIdx.z, bh = blockIdx.y, qt = blockIdx.x;
    int h = bh & 3, b = bh >> 2;
    const float* Q = g_qkv[3*axial + 0] + (bh*160 + qt*QT)*DH;
    const float* K = g_qkv[3*axial + 1] + bh*160*DH;
    const float* V = g_qkv[3*axial + 2] + bh*160*DH;

    extern __shared__ float dyn[];
    float (*Ks)[36]  = (float(*)[36])(dyn);           // 164x36
    float (*Vs)[36]  = (float(*)[36])(dyn + 5904);    // 164x36
    float (*Qs)[36]  = (float(*)[36])(dyn + 11808);   // 16x36
    float (*S)[168]  = (float(*)[168])(dyn + 12384);  // 16x168
    float* invZ      = dyn + 15072;                   // 16
    float (*Ob)[17]  = (float(*)[17])(dyn + 15088);   // 32x17

    int tid = threadIdx.x, warp = tid >> 5, lane = tid & 31;
    for (int i4 = tid; i4 < 1280; i4 += 256) {
        float4 kv = ((const float4*)K)[i4];
        float4 vv = ((const float4*)V)[i4];
        int r = i4 >> 3, cc = (i4 & 7) * 4;
        *(float4*)&Ks[r][cc] = kv;
        *(float4*)&Vs[r][cc] = vv;
    }
    if (tid < 64) {
        int i4 = tid & 31;
        int r = 160 + (i4 >> 3), cc = (i4 & 7) * 4;
        if (tid < 32) {
            float4 mk = ((const float4*)(memkv + h*NMEM*DH))[i4];
            *(float4*)&Ks[r][cc] = mk;
        } else {
            float4 mv = ((const float4*)(memkv + HEADS*NMEM*DH + h*NMEM*DH))[i4];
            *(float4*)&Vs[r][cc] = mv;
        }
    }
    for (int i4 = tid; i4 < 128; i4 += 256) {
        float4 qv = ((const float4*)Q)[i4];
        int r = i4 >> 3, cc = (i4 & 7) * 4;
        *(float4*)&Qs[r][cc] = qv;
    }
    __syncthreads();

    int qr = warp * 2;
    float s0[6], s1[6];
    #pragma unroll
    for (int j = 0; j < 6; j++) {
        int k = lane + 32*j;
        float a0 = 0.f, a1 = 0.f;
        if (k < 164) {
            #pragma unroll
            for (int d4 = 0; d4 < 8; d4++) {
                float4 kv = *(const float4*)&Ks[k][d4*4];
                float4 qa = *(const float4*)&Qs[qr][d4*4];
                float4 qb = *(const float4*)&Qs[qr+1][d4*4];
                a0 += qa.x*kv.x + qa.y*kv.y + qa.z*kv.z + qa.w*kv.w;
                a1 += qb.x*kv.x + qb.y*kv.y + qb.z*kv.z + qb.w*kv.w;
            }
        }
        s0[j] = a0; s1[j] = a1;
    }
    float mx0 = -1e30f, mx1 = -1e30f;
    #pragma unroll
    for (int j = 0; j < 6; j++)
        if (lane + 32*j < 164) { mx0 = fmaxf(mx0, s0[j]); mx1 = fmaxf(mx1, s1[j]); }
    #pragma unroll
    for (int o = 16; o; o >>= 1) {
        mx0 = fmaxf(mx0, __shfl_xor_sync(0xffffffffu, mx0, o));
        mx1 = fmaxf(mx1, __shfl_xor_sync(0xffffffffu, mx1, o));
    }
    float z0 = 0.f, z1 = 0.f;
    #pragma unroll
    for (int j = 0; j < 6; j++) {
        int k = lane + 32*j;
        if (k < 164) {
            float wgt = (k < 160) ? 160.0f : 1.0f;
            float e0 = __expf(s0[j] - mx0), e1 = __expf(s1[j] - mx1);
            S[qr][k] = e0; S[qr+1][k] = e1;
            z0 += wgt*e0; z1 += wgt*e1;
        }
    }
    #pragma unroll
    for (int o = 16; o; o >>= 1) {
        z0 += __shfl_xor_sync(0xffffffffu, z0, o);
        z1 += __shfl_xor_sync(0xffffffffu, z1, o);
    }
    if (!lane) { invZ[qr] = 1.0f / z0; invZ[qr+1] = 1.0f / z1; }
    __syncwarp();

    float acc0 = 0.f, acc1 = 0.f;
    #pragma unroll 4
    for (int k4 = 0; k4 < 41; k4++) {
        float4 e0 = *(const float4*)&S[qr][k4*4];
        float4 e1 = *(const float4*)&S[qr+1][k4*4];
        float v0 = Vs[k4*4+0][lane], v1 = Vs[k4*4+1][lane];
        float v2 = Vs[k4*4+2][lane], v3 = Vs[k4*4+3][lane];
        acc0 += e0.x*v0 + e0.y*v1 + e0.z*v2 + e0.w*v3;
        acc1 += e1.x*v0 + e1.y*v1 + e1.z*v2 + e1.w*v3;
    }
    Ob[lane][qr]     = acc0 * invZ[qr];
    Ob[lane][qr + 1] = acc1 * invZ[qr + 1];
    __syncthreads();
    float* outp = g_hoT[axial] + (size_t)(b*HID + h*DH)*160 + qt*QT;
    for (int idx = tid; idx < 32*QT; idx += 256) {
        int d = idx >> 4, q = idx & 15;
        outp[d*160 + q] = Ob[d][q];
    }
}

// ---------------- K5: fused F-dot + broadcast write ---------------------------
__global__ void __launch_bounds__(320) k_out(float* __restrict__ out) {
    int d = blockIdx.x, b = blockIdx.y;
    __shared__ float E0[128], E1[128];
    __shared__ __align__(16) float Fr[160], Fc[160];
    int t = threadIdx.x;  // 320
    if (t < 128) E0[t] = g_E[0][d*HID + t];
    else if (t < 256) E1[t - 128] = g_E[1][d*HID + (t - 128)];
    __syncthreads();
    if (t < 160) {
        const float* hp = g_hoT[0] + (size_t)b*HID*160 + t;
        float a = 0.f;
        #pragma unroll 8
        for (int hid = 0; hid < HID; hid++) a += E0[hid] * hp[hid*160];
        Fr[t] = a + g_e[0][d];
    } else {
        int p = t - 160;
        const float* hp = g_hoT[1] + (size_t)b*HID*160 + p;
        float a = 0.f;
        #pragma unroll 8
        for (int hid = 0; hid < HID; hid++) a += E1[hid] * hp[hid*160];
        Fc[p] = a + g_e[1][d];
    }
    __syncthreads();
    int m4 = t % 40, ng = t / 40;   // ng in [0,8)
    float4 cv = *(const float4*)&Fc[m4*4];
    float* op = out + ((size_t)(b*C + d)*160)*160 + m4*4;
    #pragma unroll 5
    for (int i = 0; i < 20; i++) {
        int n = ng + 8*i;
        float r = Fr[n];
        float4 v = {r + cv.x, r + cv.y, r + cv.z, r + cv.w};
        *(float4*)&op[(size_t)n*160] = v;
    }
}

// ---------------- launch --------------------------------------------------------
extern "C" void kernel_launch(void* const* d_in, const int* in_sizes, int n_in,
                              void* d_out, int out_size) {
    const float* x     = (const float*)d_in[0];
    const float* gq    = (const float*)d_in[1];
    const float* gk    = (const float*)d_in[2];
    const float* gv    = (const float*)d_in[3];
    const float* Wq    = (const float*)d_in[4];
    const float* Wk    = (const float*)d_in[5];
    const float* Wv    = (const float*)d_in[6];
    const float* memkv = (const float*)d_in[7];
    const float* Wo    = (const float*)d_in[8];
    const float* bo    = (const float*)d_in[9];
    const float* Wr    = (const float*)d_in[10];
    float* out = (float*)d_out;

    cudaFuncSetAttribute(k_attn, cudaFuncAttributeMaxDynamicSharedMemorySize, 62528);

    k_pre   <<<48 + B*160, 160>>>(x, Wr, Wo, bo);
    k_reduce<<<B*C, 256>>>(x, gv);
    k_proj  <<<dim3(80, 6), 256>>>(Wq, Wk, Wv, gq, gk);
    k_attn  <<<dim3(10, 16, 2), 256, 62528>>>(memkv);
    k_out   <<<dim3(192, 4), 320>>>(out);
}